// round 5
// baseline (speedup 1.0000x reference)
#include <cuda_runtime.h>
#include <math.h>

// ---------------------------------------------------------------------------
// B=8, Nc=1024, Nt=1024, Dx=3, Dy=32, H=128
// inputs: xc, yc, xt, W0, b0, W1, b1, W2, b2, W3, b3 (all f32)
// out: (B, Nt, 32) f32
// Single fused kernel: grid (32, 8) blocks x 256 threads, one wave.
// ---------------------------------------------------------------------------

#define B_SZ 8
#define NC 1024
#define NT 1024
#define TPB 256

typedef unsigned long long ull;

// ---------------- packed f32x2 helpers (Blackwell FFMA2) -------------------
__device__ __forceinline__ ull dup2(float x) {
    ull r; asm("mov.b64 %0, {%1, %1};" : "=l"(r) : "f"(x)); return r;
}
__device__ __forceinline__ void fma2(ull& d, ull a, ull b) {
    asm("fma.rn.f32x2 %0, %1, %2, %0;" : "+l"(d) : "l"(a), "l"(b));
}
__device__ __forceinline__ ull mul2(ull a, ull b) {
    ull r; asm("mul.rn.f32x2 %0, %1, %2;" : "=l"(r) : "l"(a), "l"(b)); return r;
}
__device__ __forceinline__ ull add2(ull a, ull b) {
    ull r; asm("add.rn.f32x2 %0, %1, %2;" : "=l"(r) : "l"(a), "l"(b)); return r;
}
__device__ __forceinline__ void unpack2(ull v, float& lo, float& hi) {
    asm("mov.b64 {%0, %1}, %2;" : "=f"(lo), "=f"(hi) : "l"(v));
}
__device__ __forceinline__ float ex2f(float x) {
    float y; asm("ex2.approx.ftz.f32 %0, %1;" : "=f"(y) : "f"(x)); return y;
}

// ---------------- shared memory arena (floats) -----------------------------
// Phase A (MLP):
#define oW   0        /* 16384: W1 then W2 */
#define ohA  16384    /* 128 rows x 36 pad = 4608 */
#define ohB  20992    /* 4608 */
#define oW0  25600    /* 384 */
#define oW3  25984    /* 384 */
#define ob0  26368
#define ob1  26496
#define ob2  26624
#define ob3  26752    /* 16 */
#define oxt  26768    /* 96 -> pad 112 */
#define oso  26880    /* 128 */
#define ASQ  27008    /* 256: q vectors (outside phase-B arena) */
#define ASL  27264    /* 32 */
#define SMEM_FLOATS 27296
// Phase B (attention), overlays phase A low arena:
#define AKV  0        /* 6 x 128 key features */
#define ASYC 768      /* 128 x 32 values */
#define ASW  4864     /* 32 targets x 132 weights (t-major) */
#define ASSC 9088     /* 32 rescale factors */
#define ARED ASW      /* 4 x 32 x 32 reduce buffers (after chunks) */

__device__ __forceinline__ void cp4(float* dst, const float* src, int n4, int tid) {
    const float4* s4 = (const float4*)src;
    float4* d4 = (float4*)dst;
    for (int i = tid; i < n4; i += TPB) d4[i] = s4[i];
}

// hidden layer: thread owns units (j, j+64) for 8 points of group g.
__device__ __forceinline__ void hidden_layer(float* S, int oin, int oout,
                                             int ob, int g, int j) {
    ull A0, A1, A2, A3, A4, A5, A6, A7;
    A0 = A1 = A2 = A3 = dup2(S[ob + j]);
    A4 = A5 = A6 = A7 = dup2(S[ob + j + 64]);
#pragma unroll 8
    for (int k = 0; k < 128; ++k) {
        const float* ap = &S[oin + k * 36 + g * 8];
        ulonglong2 p01 = *(const ulonglong2*)ap;
        ulonglong2 p23 = *(const ulonglong2*)(ap + 4);
        ull wa = dup2(S[oW + k * 128 + j]);
        ull wb = dup2(S[oW + k * 128 + j + 64]);
        fma2(A0, p01.x, wa); fma2(A1, p01.y, wa);
        fma2(A2, p23.x, wa); fma2(A3, p23.y, wa);
        fma2(A4, p01.x, wb); fma2(A5, p01.y, wb);
        fma2(A6, p23.x, wb); fma2(A7, p23.y, wb);
    }
    float v[16];
    unpack2(A0, v[0], v[1]);  unpack2(A1, v[2], v[3]);
    unpack2(A2, v[4], v[5]);  unpack2(A3, v[6], v[7]);
    unpack2(A4, v[8], v[9]);  unpack2(A5, v[10], v[11]);
    unpack2(A6, v[12], v[13]); unpack2(A7, v[14], v[15]);
    float4* r0 = (float4*)&S[oout + j * 36 + g * 8];
    r0[0] = make_float4(fmaxf(v[0], 0.f), fmaxf(v[1], 0.f), fmaxf(v[2], 0.f), fmaxf(v[3], 0.f));
    r0[1] = make_float4(fmaxf(v[4], 0.f), fmaxf(v[5], 0.f), fmaxf(v[6], 0.f), fmaxf(v[7], 0.f));
    float4* r1 = (float4*)&S[oout + (j + 64) * 36 + g * 8];
    r1[0] = make_float4(fmaxf(v[8], 0.f), fmaxf(v[9], 0.f), fmaxf(v[10], 0.f), fmaxf(v[11], 0.f));
    r1[1] = make_float4(fmaxf(v[12], 0.f), fmaxf(v[13], 0.f), fmaxf(v[14], 0.f), fmaxf(v[15], 0.f));
}

__global__ void __launch_bounds__(TPB, 2)
fused_kernel(const float* __restrict__ xc, const float* __restrict__ yc,
             const float* __restrict__ xt,
             const float* __restrict__ W0, const float* __restrict__ b0,
             const float* __restrict__ W1, const float* __restrict__ b1,
             const float* __restrict__ W2, const float* __restrict__ b2,
             const float* __restrict__ W3, const float* __restrict__ b3,
             float* __restrict__ out) {
    extern __shared__ float S[];
    int tid = threadIdx.x;
    int b = blockIdx.y;
    int t0 = blockIdx.x * 32;
    int wid = tid >> 5, lane = tid & 31;

    // ================= Phase A: MLP -> sigma -> q ==========================
    cp4(&S[oW], W1, 4096, tid);
    cp4(&S[oW0], W0, 96, tid);
    cp4(&S[oW3], W3, 96, tid);
    cp4(&S[ob0], b0, 32, tid);
    cp4(&S[ob1], b1, 32, tid);
    cp4(&S[ob2], b2, 32, tid);
    if (tid < 3) S[ob3 + tid] = b3[tid];
    if (tid < 96) S[oxt + tid] = xt[(b * NT + t0) * 3 + tid];
    __syncthreads();

    int g = tid >> 6;   // 4 groups x 8 points
    int j = tid & 63;   // units j, j+64

    // layer 0: 3 -> 128
    {
        float bb0 = S[ob0 + j], bb1 = S[ob0 + j + 64];
        float w00 = S[oW0 + j],       w01 = S[oW0 + j + 64];
        float w10 = S[oW0 + 128 + j], w11 = S[oW0 + 128 + j + 64];
        float w20 = S[oW0 + 256 + j], w21 = S[oW0 + 256 + j + 64];
        float a0[8], a1[8];
#pragma unroll
        for (int p = 0; p < 8; ++p) {
            int lp = g * 8 + p;
            float x0 = S[oxt + lp * 3 + 0];
            float x1 = S[oxt + lp * 3 + 1];
            float x2 = S[oxt + lp * 3 + 2];
            a0[p] = fmaxf(fmaf(x2, w20, fmaf(x1, w10, fmaf(x0, w00, bb0))), 0.f);
            a1[p] = fmaxf(fmaf(x2, w21, fmaf(x1, w11, fmaf(x0, w01, bb1))), 0.f);
        }
        float4* r0 = (float4*)&S[ohA + j * 36 + g * 8];
        r0[0] = make_float4(a0[0], a0[1], a0[2], a0[3]);
        r0[1] = make_float4(a0[4], a0[5], a0[6], a0[7]);
        float4* r1 = (float4*)&S[ohA + (j + 64) * 36 + g * 8];
        r1[0] = make_float4(a1[0], a1[1], a1[2], a1[3]);
        r1[1] = make_float4(a1[4], a1[5], a1[6], a1[7]);
    }
    __syncthreads();

    // prefetch W2 into registers (hidden behind layer-1 compute)
    float4 w2r[16];
#pragma unroll
    for (int i = 0; i < 16; ++i) w2r[i] = ((const float4*)W2)[tid + 256 * i];

    hidden_layer(S, ohA, ohB, ob1, g, j);    // layer 1 (W1)
    __syncthreads();
#pragma unroll
    for (int i = 0; i < 16; ++i) ((float4*)&S[oW])[tid + 256 * i] = w2r[i];
    __syncthreads();
    hidden_layer(S, ohB, ohA, ob2, g, j);    // layer 2 (W2)
    __syncthreads();

    // output layer 128 -> 3: warps 0..2 (d = wid), lane = point
    if (wid < 3) {
        int d = wid;
        float a0 = 0.f, a1 = 0.f, a2 = 0.f, a3 = 0.f;
#pragma unroll 4
        for (int k = 0; k < 128; k += 4) {
            a0 = fmaf(S[ohA + (k + 0) * 36 + lane], S[oW3 + (k + 0) * 3 + d], a0);
            a1 = fmaf(S[ohA + (k + 1) * 36 + lane], S[oW3 + (k + 1) * 3 + d], a1);
            a2 = fmaf(S[ohA + (k + 2) * 36 + lane], S[oW3 + (k + 2) * 3 + d], a2);
            a3 = fmaf(S[ohA + (k + 3) * 36 + lane], S[oW3 + (k + 3) * 3 + d], a3);
        }
        S[oso + lane * 4 + d] = S[ob3 + d] + ((a0 + a1) + (a2 + a3));
    }
    __syncthreads();

    // epilogue: sigma = exp(o), build q (log2 domain)
    if (tid < 32) {
        float o0 = S[oso + tid * 4 + 0];
        float o1 = S[oso + tid * 4 + 1];
        float o2 = S[oso + tid * 4 + 2];
        float s0 = expf(o0), s1 = expf(o1), s2 = expf(o2);
        float x0 = S[oxt + tid * 3 + 0];
        float x1 = S[oxt + tid * 3 + 1];
        float x2 = S[oxt + tid * 3 + 2];
        const float L2E = 1.44269504088896340736f;
        float c6 = -(s0 * x0 * x0 + s1 * x1 * x1 + s2 * x2 * x2) * L2E;
        float4* qd = (float4*)&S[ASQ + tid * 8];
        qd[0] = make_float4(2.f * s0 * x0 * L2E, 2.f * s1 * x1 * L2E,
                            2.f * s2 * x2 * L2E, -s0 * L2E);
        qd[1] = make_float4(-s1 * L2E, -s2 * L2E, c6, 0.f);
    }
    __syncthreads();

    // ================= Phase B: streaming softmax-attention ================
    // softmax mapping: warp wid owns targets wid*4+tsub; csub = context subset
    int tsub = lane >> 3, csub = lane & 7;
    int tq = wid * 4 + tsub;
    ull q0d = dup2(S[ASQ + tq * 8 + 0]);
    ull q1d = dup2(S[ASQ + tq * 8 + 1]);
    ull q2d = dup2(S[ASQ + tq * 8 + 2]);
    ull q3d = dup2(S[ASQ + tq * 8 + 3]);
    ull q4d = dup2(S[ASQ + tq * 8 + 4]);
    ull q5d = dup2(S[ASQ + tq * 8 + 5]);
    ull q6d = dup2(S[ASQ + tq * 8 + 6]);
    float mrun = -1e30f, lrun = 0.f;

    // GEMM mapping: warp = c-split (16 contexts), thread owns targets tg+8i,
    // dy dims dg*8..dg*8+8
    int tg = lane >> 2, dg = lane & 3;

    ull acc[4][4];
#pragma unroll
    for (int i = 0; i < 4; ++i)
#pragma unroll
        for (int d2 = 0; d2 < 4; ++d2) acc[i][d2] = 0ull;

    for (int ch = 0; ch < 8; ++ch) {
        int cbase = ch * 128;
        __syncthreads();   // prior chunk consumers done

        if (tid < 128) {   // key features (SoA)
            const float* xp = &xc[(b * NC + cbase + tid) * 3];
            float x0 = xp[0], x1 = xp[1], x2 = xp[2];
            S[AKV + tid] = x0;
            S[AKV + 128 + tid] = x1;
            S[AKV + 256 + tid] = x2;
            S[AKV + 384 + tid] = x0 * x0;
            S[AKV + 512 + tid] = x1 * x1;
            S[AKV + 640 + tid] = x2 * x2;
        } else {           // value tile copy
            int t2 = tid - 128;
            const float4* ys = (const float4*)&yc[(b * NC + cbase) * 32];
            float4* yd = (float4*)&S[ASYC];
#pragma unroll
            for (int r = 0; r < 8; ++r) yd[t2 + 128 * r] = ys[t2 + 128 * r];
        }
        __syncthreads();

        // ---- logits: 16 contexts per lane, f32x2 pairs ----
        float preg[16];
        float lmax = -1e30f;
#pragma unroll
        for (int i4 = 0; i4 < 4; ++i4) {
            int c0 = csub * 16 + i4 * 4;
            ulonglong2 f0 = *(const ulonglong2*)&S[AKV + c0];
            ulonglong2 f1 = *(const ulonglong2*)&S[AKV + 128 + c0];
            ulonglong2 f2 = *(const ulonglong2*)&S[AKV + 256 + c0];
            ulonglong2 f3 = *(const ulonglong2*)&S[AKV + 384 + c0];
            ulonglong2 f4 = *(const ulonglong2*)&S[AKV + 512 + c0];
            ulonglong2 f5 = *(const ulonglong2*)&S[AKV + 640 + c0];
            ull P01 = q6d, P23 = q6d;
            fma2(P01, f0.x, q0d); fma2(P23, f0.y, q0d);
            fma2(P01, f1.x, q1d); fma2(P23, f1.y, q1d);
            fma2(P01, f2.x, q2d); fma2(P23, f2.y, q2d);
            fma2(P01, f3.x, q3d); fma2(P23, f3.y, q3d);
            fma2(P01, f4.x, q4d); fma2(P23, f4.y, q4d);
            fma2(P01, f5.x, q5d); fma2(P23, f5.y, q5d);
            unpack2(P01, preg[i4 * 4 + 0], preg[i4 * 4 + 1]);
            unpack2(P23, preg[i4 * 4 + 2], preg[i4 * 4 + 3]);
            lmax = fmaxf(lmax, fmaxf(fmaxf(preg[i4 * 4], preg[i4 * 4 + 1]),
                                     fmaxf(preg[i4 * 4 + 2], preg[i4 * 4 + 3])));
        }
        // per-target max over 8 csub lanes
        lmax = fmaxf(lmax, __shfl_xor_sync(0xffffffffu, lmax, 1));
        lmax = fmaxf(lmax, __shfl_xor_sync(0xffffffffu, lmax, 2));
        lmax = fmaxf(lmax, __shfl_xor_sync(0xffffffffu, lmax, 4));
        float mn = fmaxf(mrun, lmax);
        float scl = ex2f(mrun - mn);
        mrun = mn;

        float lsum = 0.f;
#pragma unroll
        for (int i = 0; i < 16; ++i) {
            preg[i] = ex2f(preg[i] - mn);
            lsum += preg[i];
        }
        lsum += __shfl_xor_sync(0xffffffffu, lsum, 1);
        lsum += __shfl_xor_sync(0xffffffffu, lsum, 2);
        lsum += __shfl_xor_sync(0xffffffffu, lsum, 4);
        lrun = fmaf(lrun, scl, lsum);

        // store weights t-major (stride 132)
        {
            float4* wd = (float4*)&S[ASW + tq * 132 + csub * 16];
            wd[0] = make_float4(preg[0], preg[1], preg[2], preg[3]);
            wd[1] = make_float4(preg[4], preg[5], preg[6], preg[7]);
            wd[2] = make_float4(preg[8], preg[9], preg[10], preg[11]);
            wd[3] = make_float4(preg[12], preg[13], preg[14], preg[15]);
        }
        if (csub == 0) S[ASSC + tq] = scl;
        __syncthreads();

        // ---- rescale accumulators ----
#pragma unroll
        for (int i = 0; i < 4; ++i) {
            ull sc = dup2(S[ASSC + tg + 8 * i]);
#pragma unroll
            for (int d2 = 0; d2 < 4; ++d2) acc[i][d2] = mul2(acc[i][d2], sc);
        }

        // ---- value GEMM: warp wid covers contexts wid*16..wid*16+16 ----
#pragma unroll
        for (int k4 = 0; k4 < 4; ++k4) {
            int c0 = wid * 16 + k4 * 4;
            float4 wv0 = *(const float4*)&S[ASW + (tg     ) * 132 + c0];
            float4 wv1 = *(const float4*)&S[ASW + (tg +  8) * 132 + c0];
            float4 wv2 = *(const float4*)&S[ASW + (tg + 16) * 132 + c0];
            float4 wv3 = *(const float4*)&S[ASW + (tg + 24) * 132 + c0];
#define DO_CI(CI, COMP)                                                        \
            {                                                                  \
                const float* yp = &S[ASYC + (c0 + CI) * 32 + dg * 8];          \
                ulonglong2 ya = *(const ulonglong2*)yp;                        \
                ulonglong2 yb = *(const ulonglong2*)(yp + 4);                  \
                ull w;                                                         \
                w = dup2(wv0.COMP);                                            \
                fma2(acc[0][0], ya.x, w); fma2(acc[0][1], ya.y, w);            \
                fma2(acc[0][2], yb.x, w); fma2(acc[0][3], yb.y, w);            \
                w = dup2(wv1.COMP);                                            \
                fma2(acc[1][0], ya.x, w); fma2(acc[1][1], ya.y, w);            \
                fma2(acc[1][2], yb.x, w); fma2(acc[1][3], yb.y, w);            \
                w = dup2(wv2.COMP);                                            \
                fma2(acc[2][0], ya.x, w); fma2(acc[2][1], ya.y, w);            \
                fma2(acc[2][2], yb.x, w); fma2(acc[2][3], yb.y, w);            \
                w = dup2(wv3.COMP);                                            \
                fma2(acc[3][0], ya.x, w); fma2(acc[3][1], ya.y, w);            \
                fma2(acc[3][2], yb.x, w); fma2(acc[3][3], yb.y, w);            \
            }
            DO_CI(0, x) DO_CI(1, y) DO_CI(2, z) DO_CI(3, w)
#undef DO_CI
        }
    }
    __syncthreads();   // weights/values dead; reuse ASW as reduce buffer

    if (csub == 0) S[ASL + tq] = lrun;

    // 8-way c-split reduction: warps 0-3 store, warps 4-7 add
    if (wid < 4) {
#pragma unroll
        for (int i = 0; i < 4; ++i) {
            int t = tg + 8 * i;
            ulonglong2* dst = (ulonglong2*)&S[ARED + wid * 1024 + t * 32 + dg * 8];
            ulonglong2 v0, v1;
            v0.x = acc[i][0]; v0.y = acc[i][1];
            v1.x = acc[i][2]; v1.y = acc[i][3];
            dst[0] = v0; dst[1] = v1;
        }
    }
    __syncthreads();
    if (wid >= 4) {
#pragma unroll
        for (int i = 0; i < 4; ++i) {
            int t = tg + 8 * i;
            ulonglong2* p = (ulonglong2*)&S[ARED + (wid - 4) * 1024 + t * 32 + dg * 8];
            ulonglong2 v0 = p[0], v1 = p[1];
            v0.x = add2(v0.x, acc[i][0]); v0.y = add2(v0.y, acc[i][1]);
            v1.x = add2(v1.x, acc[i][2]); v1.y = add2(v1.y, acc[i][3]);
            p[0] = v0; p[1] = v1;
        }
    }
    __syncthreads();

    // final: sum 4 buffers, normalize, store
    {
        int t = tid >> 3, d8 = tid & 7;
        ull r0 = 0ull, r1 = 0ull;
#pragma unroll
        for (int sI = 0; sI < 4; ++sI) {
            ulonglong2 v = *(const ulonglong2*)&S[ARED + sI * 1024 + t * 32 + d8 * 4];
            r0 = add2(r0, v.x);
            r1 = add2(r1, v.y);
        }
        ull inv = dup2(1.0f / S[ASL + t]);
        r0 = mul2(r0, inv);
        r1 = mul2(r1, inv);
        ulonglong2 o; o.x = r0; o.y = r1;
        *(ulonglong2*)&out[(b * NT + t0 + t) * 32 + d8 * 4] = o;
    }
}

// ============================== launch =====================================
extern "C" void kernel_launch(void* const* d_in, const int* in_sizes, int n_in,
                              void* d_out, int out_size) {
    (void)in_sizes; (void)n_in; (void)out_size;
    const float* xc = (const float*)d_in[0];
    const float* yc = (const float*)d_in[1];
    const float* xt = (const float*)d_in[2];
    const float* W0 = (const float*)d_in[3];
    const float* b0 = (const float*)d_in[4];
    const float* W1 = (const float*)d_in[5];
    const float* b1 = (const float*)d_in[6];
    const float* W2 = (const float*)d_in[7];
    const float* b2 = (const float*)d_in[8];
    const float* W3 = (const float*)d_in[9];
    const float* b3 = (const float*)d_in[10];
    float* out = (float*)d_out;

    size_t smem = SMEM_FLOATS * sizeof(float);
    cudaFuncSetAttribute(fused_kernel, cudaFuncAttributeMaxDynamicSharedMemorySize,
                         (int)smem);

    fused_kernel<<<dim3(NT / 32, B_SZ), TPB, smem>>>(
        xc, yc, xt, W0, b0, W1, b1, W2, b2, W3, b3, out);
}